// round 15
// baseline (speedup 1.0000x reference)
#include <cuda_runtime.h>

#define F_IN     65536
#define NN       100
#define CC       60
#define NSTATE   6003
#define NEDGE    2000
#define SPLIT    128
#define CHUNK    512      // F_IN / SPLIT
#define KT       32
#define FCB      32
#define ASPITCH  34       // pad so m-group strides hit distinct banks (136B, float2-aligned)

// ---- scratch (static device globals; no allocation allowed) ----
__device__ float g_P[NN * NN];
__device__ float g_P2[NN * NN];
__device__ float g_Ypart[(size_t)SPLIT * 6 * NN * CC];   // 18.4 MB partials
__device__ float g_Y[6 * NN * CC];
__device__ float g_state[2 * NSTATE];
__device__ float g_fcpart[FCB * 101];

// ---- packed f32x2 helpers ----
__device__ __forceinline__ unsigned long long dup_f32(float x) {
    unsigned long long r;
    unsigned int xi = __float_as_uint(x);
    asm("mov.b64 %0, {%1, %1};" : "=l"(r) : "r"(xi));
    return r;
}
__device__ __forceinline__ void fma2(unsigned long long& d, unsigned long long a,
                                     unsigned long long b) {
    asm("fma.rn.f32x2 %0, %1, %2, %0;" : "+l"(d) : "l"(a), "l"(b));
}

// ============================================================
// 1) Build dense scaled-Laplacian P (L_hat off-diagonals) and P2 = P@P.
//    deg = out-degree over src; norm_e = -dis[src]*dis[dst]; P[dst][src] += norm.
// ============================================================
__global__ void prep_kernel(const int* __restrict__ ei) {
    __shared__ float degS[NN];
    __shared__ float disS[NN];
    __shared__ float Ps[NN * NN];
    const int tid = threadIdx.x;
    for (int i = tid; i < NN; i += blockDim.x) degS[i] = 0.f;
    for (int i = tid; i < NN * NN; i += blockDim.x) Ps[i] = 0.f;
    __syncthreads();
    for (int e = tid; e < NEDGE; e += blockDim.x)
        atomicAdd(&degS[ei[e]], 1.0f);
    __syncthreads();
    for (int i = tid; i < NN; i += blockDim.x)
        disS[i] = degS[i] > 0.f ? rsqrtf(degS[i]) : 0.f;
    __syncthreads();
    for (int e = tid; e < NEDGE; e += blockDim.x) {
        int s = ei[e], d = ei[NEDGE + e];
        atomicAdd(&Ps[d * NN + s], -disS[s] * disS[d]);
    }
    __syncthreads();
    for (int i = tid; i < NN * NN; i += blockDim.x) g_P[i] = Ps[i];
    for (int i = tid; i < NN * NN; i += blockDim.x) {
        int r = i / NN, c = i % NN;
        float s = 0.f;
        for (int m = 0; m < NN; ++m) s += Ps[r * NN + m] * Ps[m * NN + c];
        g_P2[i] = s;
    }
}

// ============================================================
// 2) Fused 6-way split-K GEMM: Y_k^partial = x_chunk @ Wk_chunk
//    One CTA: one Cheb tap k3, both actor+critic, one 512-wide F chunk.
//    Thread tile: 4 m-rows x 6 c-cols x 2 branches, f32x2 accumulators.
// ============================================================
__global__ void __launch_bounds__(256, 3)
gemm_kernel(const float* __restrict__ x, const float* __restrict__ aw,
            const float* __restrict__ cw) {
    const int b     = blockIdx.x;
    const int k3    = b % 3;
    const int chunk = b / 3;
    const float* Wa = aw + (size_t)k3 * F_IN * CC;
    const float* Wc = cw + (size_t)k3 * F_IN * CC;

    __shared__ float As[NN * ASPITCH];   // 13.6 KB
    __shared__ float Bsa[KT * CC];       // 7.68 KB
    __shared__ float Bsc[KT * CC];       // 7.68 KB

    const int tid    = threadIdx.x;
    const bool active = tid < 250;
    const int cg = tid % 10, mg = tid / 10;
    const int c0 = cg * 6, m0 = mg * 4;

    unsigned long long acc[2][4][3];
#pragma unroll
    for (int u = 0; u < 2; ++u)
#pragma unroll
        for (int r = 0; r < 4; ++r)
#pragma unroll
            for (int j = 0; j < 3; ++j) acc[u][r][j] = 0ull;

    const int fbase = chunk * CHUNK;
    for (int t = 0; t < CHUNK / KT; ++t) {
        const int f0 = fbase + t * KT;
        // stage As: 100 rows x 32 floats (800 float4 loads)
        for (int idx = tid; idx < 800; idx += 256) {
            int row = idx >> 3, c4 = idx & 7;
            float4 v = *reinterpret_cast<const float4*>(x + (size_t)row * F_IN + f0 + c4 * 4);
            float2* p = reinterpret_cast<float2*>(&As[row * ASPITCH + c4 * 4]);
            p[0] = make_float2(v.x, v.y);
            p[1] = make_float2(v.z, v.w);
        }
        // stage both weight tiles: each 32x60 floats contiguous (480 float4)
        const float4* wa4 = reinterpret_cast<const float4*>(Wa + (size_t)f0 * CC);
        const float4* wc4 = reinterpret_cast<const float4*>(Wc + (size_t)f0 * CC);
        for (int idx = tid; idx < 480; idx += 256) {
            reinterpret_cast<float4*>(Bsa)[idx] = wa4[idx];
            reinterpret_cast<float4*>(Bsc)[idx] = wc4[idx];
        }
        __syncthreads();
        if (active) {
#pragma unroll 8
            for (int kk = 0; kk < KT; ++kk) {
                unsigned long long a0 = dup_f32(As[(m0 + 0) * ASPITCH + kk]);
                unsigned long long a1 = dup_f32(As[(m0 + 1) * ASPITCH + kk]);
                unsigned long long a2 = dup_f32(As[(m0 + 2) * ASPITCH + kk]);
                unsigned long long a3 = dup_f32(As[(m0 + 3) * ASPITCH + kk]);
                const unsigned long long* ba =
                    reinterpret_cast<const unsigned long long*>(&Bsa[kk * CC + c0]);
                const unsigned long long* bc =
                    reinterpret_cast<const unsigned long long*>(&Bsc[kk * CC + c0]);
                unsigned long long b0 = ba[0], b1 = ba[1], b2 = ba[2];
                unsigned long long d0 = bc[0], d1 = bc[1], d2 = bc[2];
                fma2(acc[0][0][0], a0, b0); fma2(acc[0][0][1], a0, b1); fma2(acc[0][0][2], a0, b2);
                fma2(acc[1][0][0], a0, d0); fma2(acc[1][0][1], a0, d1); fma2(acc[1][0][2], a0, d2);
                fma2(acc[0][1][0], a1, b0); fma2(acc[0][1][1], a1, b1); fma2(acc[0][1][2], a1, b2);
                fma2(acc[1][1][0], a1, d0); fma2(acc[1][1][1], a1, d1); fma2(acc[1][1][2], a1, d2);
                fma2(acc[0][2][0], a2, b0); fma2(acc[0][2][1], a2, b1); fma2(acc[0][2][2], a2, b2);
                fma2(acc[1][2][0], a2, d0); fma2(acc[1][2][1], a2, d1); fma2(acc[1][2][2], a2, d2);
                fma2(acc[0][3][0], a3, b0); fma2(acc[0][3][1], a3, b1); fma2(acc[0][3][2], a3, b2);
                fma2(acc[1][3][0], a3, d0); fma2(acc[1][3][1], a3, d1); fma2(acc[1][3][2], a3, d2);
            }
        }
        __syncthreads();
    }
    if (active) {
#pragma unroll
        for (int u = 0; u < 2; ++u) {
            float* out = g_Ypart + ((size_t)chunk * 6 + u * 3 + k3) * (NN * CC);
#pragma unroll
            for (int r = 0; r < 4; ++r)
#pragma unroll
                for (int j = 0; j < 3; ++j)
                    *reinterpret_cast<float2*>(&out[(m0 + r) * CC + c0 + 2 * j]) =
                        *reinterpret_cast<float2*>(&acc[u][r][j]);
        }
    }
}

// ============================================================
// 3) Deterministic split-K reduction: Y[k6][n][c] = sum_s Ypart[s][k6][n][c]
// ============================================================
__global__ void reduce_kernel() {
    int j = blockIdx.x * 256 + threadIdx.x;
    if (j >= 6 * NN * CC) return;
    float s = 0.f;
#pragma unroll 8
    for (int p = 0; p < SPLIT; ++p) s += g_Ypart[(size_t)p * (6 * NN * CC) + j];
    g_Y[j] = s;
}

// ============================================================
// 4) Cheb recombination + bias + tanh + extras:
//    emb = Y0 - Y2 + P@Y1 + 2*P2@Y2 + b ; state = tanh(emb), extras appended
// ============================================================
__global__ void combine_kernel(const float* __restrict__ ab, const float* __restrict__ cb,
                               const float* __restrict__ vcpu, const float* __restrict__ vbw,
                               const float* __restrict__ vpend) {
    const int br = blockIdx.y;   // 0=actor, 1=critic
    const int n  = blockIdx.x;
    const int c  = threadIdx.x;  // 64 threads
    __shared__ float Pr[NN], P2r[NN];
    for (int i = c; i < NN; i += 64) {
        Pr[i]  = g_P[n * NN + i];
        P2r[i] = g_P2[n * NN + i];
    }
    __syncthreads();
    const float* Yb = g_Y + (size_t)br * 3 * NN * CC;
    if (c < CC) {
        const float* bias = br ? cb : ab;
        float v = Yb[n * CC + c] - Yb[2 * NN * CC + n * CC + c] + bias[c];
        float s1 = 0.f, s2 = 0.f;
        for (int m = 0; m < NN; ++m) {
            s1 += Pr[m]  * Yb[NN * CC + m * CC + c];
            s2 += P2r[m] * Yb[2 * NN * CC + m * CC + c];
        }
        v += s1 + 2.f * s2;
        g_state[br * NSTATE + n * CC + c] = tanhf(v);
    }
    if (n == 0 && c == 63) {
        g_state[br * NSTATE + 6000] = vcpu[0];
        g_state[br * NSTATE + 6001] = vbw[0];
        g_state[br * NSTATE + 6002] = vpend[0];
    }
}

// ============================================================
// 5) Final FC: logits = state_a @ afw (+b), value = state_c @ cfw (+b)
//    Split over i with fixed partials (deterministic), then reduce.
// ============================================================
#define FC_SEG 188   // 32 * 188 = 6016 >= 6003
__global__ void fc_partial_kernel(const float* __restrict__ afw, const float* __restrict__ cfw) {
    const int blk = blockIdx.x;
    const int t   = threadIdx.x;
    const int i0  = blk * FC_SEG;
    const int i1  = min(i0 + FC_SEG, NSTATE);
    __shared__ float sa[FC_SEG], sc[FC_SEG];
    for (int i = t; i < i1 - i0; i += 128) {
        sa[i] = g_state[i0 + i];
        sc[i] = g_state[NSTATE + i0 + i];
    }
    __syncthreads();
    if (t < 100) {
        float s = 0.f;
        for (int i = i0; i < i1; ++i) s += sa[i - i0] * afw[(size_t)i * 100 + t];
        g_fcpart[blk * 101 + t] = s;
    } else if (t == 100) {
        float s = 0.f;
        for (int i = i0; i < i1; ++i) s += sc[i - i0] * cfw[i];
        g_fcpart[blk * 101 + 100] = s;
    }
}

__global__ void fc_final_kernel(const float* __restrict__ afb, const float* __restrict__ cfb,
                                float* __restrict__ out) {
    const int t = threadIdx.x;
    if (t < 100) {
        float s = afb[t];
#pragma unroll
        for (int b = 0; b < FCB; ++b) s += g_fcpart[b * 101 + t];
        out[t] = s;
    } else if (t == 100) {
        float s = cfb[0];
#pragma unroll
        for (int b = 0; b < FCB; ++b) s += g_fcpart[b * 101 + 100];
        out[100] = s;
    }
}

// ============================================================
// kernel_launch — graph-capturable, allocation-free
// inputs (metadata order): substrate_features, edge_index, v_cpu, v_bw,
//   num_pending, actor_w, actor_b, critic_w, critic_b, actor_fc_w,
//   actor_fc_b, critic_fc_w, critic_fc_b
// output: logits[100] then value[1] (float32, 101 elements)
// ============================================================
extern "C" void kernel_launch(void* const* d_in, const int* in_sizes, int n_in,
                              void* d_out, int out_size) {
    const float* x     = (const float*)d_in[0];
    const int*   ei    = (const int*)d_in[1];
    const float* vcpu  = (const float*)d_in[2];
    const float* vbw   = (const float*)d_in[3];
    const float* vpend = (const float*)d_in[4];
    const float* aw    = (const float*)d_in[5];
    const float* ab    = (const float*)d_in[6];
    const float* cw    = (const float*)d_in[7];
    const float* cb    = (const float*)d_in[8];
    const float* afw   = (const float*)d_in[9];
    const float* afb   = (const float*)d_in[10];
    const float* cfw   = (const float*)d_in[11];
    const float* cfb   = (const float*)d_in[12];
    float* out = (float*)d_out;
    (void)in_sizes; (void)n_in; (void)out_size;

    prep_kernel<<<1, 1024>>>(ei);
    gemm_kernel<<<3 * SPLIT, 256>>>(x, aw, cw);
    reduce_kernel<<<(6 * NN * CC + 255) / 256, 256>>>();
    combine_kernel<<<dim3(NN, 2), 64>>>(ab, cb, vcpu, vbw, vpend);
    fc_partial_kernel<<<FCB, 128>>>(afw, cfw);
    fc_final_kernel<<<1, 128>>>(afb, cfb, out);
}